// round 11
// baseline (speedup 1.0000x reference)
#include <cuda_runtime.h>
#include <cuda_fp16.h>
#include <cstdint>

#define BB 32
#define SS 2048
#define DD 1024   // 2H

// ---- scores GEMM tiling (legacy mma.sync; tcgen05 not emittable: PTX target is sm_103) ----
#define M_CTA 64            // keys rows per CTA
#define KS 1032             // keys smem row stride in halfs (2064B, ldmatrix conflict-free)
#define UAS 72              // ua smem row stride in halfs (144B = 9*16B, conflict-free)
#define UA_STG 36864        // bytes per ua stage: 256 rows * 144B
#define KEYS_BYTES 132096   // 64 * 2064
#define UA_OFF   KEYS_BYTES                 // 132096
#define QW_OFF   (UA_OFF + 2 * UA_STG)      // 205824
#define VA_OFF   (QW_OFF + 4096)            // 209920
#define SACC_OFF (VA_OFF + 4096)            // 214016
#define MBAR_OFF (SACC_OFF + 1024)          // 215040: full0,full1,empty0,empty1 (8B each)
#define SMEM_DYN 215552

// ---------------- scratch (device globals; no runtime allocation) ----------------
__device__ __align__(16) __half g_Ua_t[DD * DD];   // 2 MB: tiles of (nc,kc) = 256n x 64k contiguous
__device__ float g_qW[BB * DD];                    // q@Wa.T + Wa_b + Ua_b
__device__ float g_scores[BB * SS];
__device__ float g_ctx_part[4 * BB * DD];
__device__ int g_probe_sink;

// ---------------- helpers ----------------
static __device__ __forceinline__ float tanh_approx(float x) {
    float r;
    asm("tanh.approx.f32 %0, %1;" : "=f"(r) : "f"(x));
    return r;
}
static __device__ __forceinline__ uint32_t smem_u32(const void* p) {
    uint32_t a;
    asm("{ .reg .u64 t; cvta.to.shared.u64 t, %1; cvt.u32.u64 %0, t; }" : "=r"(a) : "l"(p));
    return a;
}
static __device__ __forceinline__ void cp16(uint32_t dst, const void* src) {
    asm volatile("cp.async.cg.shared.global [%0], [%1], 16;\n" :: "r"(dst), "l"(src));
}

#define MBARRIER_INIT(addr, cnt) \
    asm volatile("mbarrier.init.shared.b64 [%0], %1;" :: "r"((uint32_t)(addr)), "r"((uint32_t)(cnt)) : "memory")
#define MBARRIER_ARRIVE(addr) \
    asm volatile("mbarrier.arrive.release.cta.shared.b64 _, [%0];" :: "r"((uint32_t)(addr)) : "memory")
#define CP_ASYNC_MBAR_ARRIVE_NOINC(addr) \
    asm volatile("cp.async.mbarrier.arrive.noinc.shared.b64 [%0];" :: "r"((uint32_t)(addr)) : "memory")
// acquire wait: consumers (generic LDS reads follow)
#define MBARRIER_WAIT_PARITY(addr, phase) do { \
    uint32_t _mbar = (uint32_t)(addr); uint32_t _par = (uint32_t)(phase); uint32_t _done; \
    asm volatile("{\n\t.reg .pred p;\n\tmbarrier.try_wait.parity.acquire.cta.shared::cta.b64 p, [%1], %2;\n\tselp.b32 %0, 1, 0, p;\n\t}" \
        : "=r"(_done) : "r"(_mbar), "r"(_par) : "memory"); \
    if (!_done) { \
        asm volatile("{\n\t.reg .pred P1;\n\tWAIT_LOOP_%=:\n\tmbarrier.try_wait.parity.acquire.cta.shared::cta.b64 P1, [%0], %1, 0x989680;\n\t@P1 bra.uni WAIT_DONE_%=;\n\tbra.uni WAIT_LOOP_%=;\n\tWAIT_DONE_%=:\n\t}" \
            :: "r"(_mbar), "r"(_par) : "memory"); \
    } } while (0)
// relaxed wait: producers only (post-wait SMEM writes are async-proxy cp.async)
#define MBARRIER_WAIT_PARITY_RELAXED(addr, phase) do { \
    uint32_t _mbar = (uint32_t)(addr); uint32_t _par = (uint32_t)(phase); uint32_t _done; \
    asm volatile("{\n\t.reg .pred p;\n\tmbarrier.try_wait.parity.relaxed.cta.shared::cta.b64 p, [%1], %2;\n\tselp.b32 %0, 1, 0, p;\n\t}" \
        : "=r"(_done) : "r"(_mbar), "r"(_par) : "memory"); \
    if (!_done) { \
        asm volatile("{\n\t.reg .pred P1;\n\tWAIT_LOOP_%=:\n\tmbarrier.try_wait.parity.relaxed.cta.shared::cta.b64 P1, [%0], %1, 0x989680;\n\t@P1 bra.uni WAIT_DONE_%=;\n\tbra.uni WAIT_LOOP_%=;\n\tWAIT_DONE_%=:\n\t}" \
            :: "r"(_mbar), "r"(_par) : "memory"); \
    } } while (0)

#define LDSM4(r0, r1, r2, r3, addr) \
    asm volatile("ldmatrix.sync.aligned.m8n8.x4.shared.b16 {%0,%1,%2,%3}, [%4];" \
        : "=r"(r0), "=r"(r1), "=r"(r2), "=r"(r3) : "r"(addr))

// f16-accumulate HMMA (2x issue rate vs f32-acc); chain limited to 128k, then promoted.
#define MMA16816H(d0, d1, a0, a1, a2, a3, b0, b1) \
    asm volatile("mma.sync.aligned.m16n8k16.row.col.f16.f16.f16.f16 " \
        "{%0,%1}, {%2,%3,%4,%5}, {%6,%7}, {%0,%1};\n" \
        : "+r"(d0), "+r"(d1) \
        : "r"(a0), "r"(a1), "r"(a2), "r"(a3), "r"(b0), "r"(b1))

// ---------------- kernel: profiling alignment probe (no-op) ----------------
__global__ void probe_kernel() { if (threadIdx.x == 1024) g_probe_sink = 1; }

// ---------------- kernel 0a: Ua -> fp16, tiled (nc,kc) chunks of 256n x 64k ----------------
__global__ void cvt_ua_kernel(const float* __restrict__ Ua) {
    int i = blockIdx.x * 256 + threadIdx.x;          // 0..262143 (float4 units)
    float4 v = reinterpret_cast<const float4*>(Ua)[i];
    int n = i >> 8;                                   // 0..1023
    int k4 = (i & 255) * 4;                           // 0..1020
    int tile = (n >> 8) * 16 + (k4 >> 6);
    __half2* dst = reinterpret_cast<__half2*>(g_Ua_t + (size_t)tile * 16384 + (n & 255) * 64 + (k4 & 63));
    dst[0] = __floats2half2_rn(v.x, v.y);
    dst[1] = __floats2half2_rn(v.z, v.w);
}

// ---------------- kernel 0b: qW[b][n] = qcat[b].Wa_w[n] + Wa_b[n] + Ua_b[n] ----------------
__global__ void qw_kernel(const float* __restrict__ query, const float* __restrict__ Wa_w,
                          const float* __restrict__ Wa_b, const float* __restrict__ Ua_b) {
    __shared__ float qc[DD];
    const int b = blockIdx.y, nb = blockIdx.x;
    const int t = threadIdx.x;                       // 128 threads
    #pragma unroll
    for (int i = 0; i < 8; i++) {
        int k = i * 128 + t;
        qc[k] = (k < 512) ? query[(b * 4 + 1) * 512 + k]
                          : query[(b * 4 + 3) * 512 + (k - 512)];
    }
    __syncthreads();
    const int lane = t & 31, w = t >> 5;
    for (int i = 0; i < 32; i++) {
        int n = nb * 128 + w * 32 + i;
        const float* wr = Wa_w + (size_t)n * DD;
        float acc = 0.f;
        #pragma unroll
        for (int j = 0; j < 32; j++) acc += qc[j * 32 + lane] * wr[j * 32 + lane];
        #pragma unroll
        for (int o = 16; o; o >>= 1) acc += __shfl_xor_sync(0xffffffffu, acc, o);
        if (lane == 0) g_qW[b * DD + n] = acc + Wa_b[n] + Ua_b[n];
    }
}

// ---------------- kernel 1: warp-specialized HMMA(f16-acc) GEMM + tanh + Va reduction -----
// 384 threads = 12 warps. Warps 0-3: Ua producers (low wid -> low arbiter priority).
// Warps 4-11: consumers; cw = warp-4: wm = cw&1 (2 x m32), wn = cw>>1 (4 x n64). Tile 64m x 256n.
__global__ __launch_bounds__(384, 1) void scores_kernel(
    const float* __restrict__ keys, const float* __restrict__ Va_w)
{
    extern __shared__ char sm[];
    __half* keys_s = (__half*)sm;
    float* qw_s = (float*)(sm + QW_OFF);
    float* va_s = (float*)(sm + VA_OFF);
    float* sacc = (float*)(sm + SACC_OFF);           // [4][64]

    const int t = threadIdx.x, l = t & 31, warp = t >> 5;
    const uint32_t sbase = smem_u32(sm);
    const uint32_t ua_base = sbase + UA_OFF;
    const uint32_t mb_full0 = sbase + MBAR_OFF;       // +0,+8: full[2]; +16,+24: empty[2]
    const int mblk = blockIdx.x;                     // 1024 blocks
    const int b = mblk >> 5;
    const int s0 = (mblk & 31) * M_CTA;

    if (t == 0) {
        MBARRIER_INIT(mb_full0 + 0, 128);   // full[0]: 128 producer async-arrivals
        MBARRIER_INIT(mb_full0 + 8, 128);   // full[1]
        MBARRIER_INIT(mb_full0 + 16, 8);    // empty[0]: lane-0 arrive from each consumer warp
        MBARRIER_INIT(mb_full0 + 24, 8);    // empty[1]
    }
    __syncthreads();

    if (warp < 4) {
        // ================= PRODUCERS (threads 0..127) =================
        const int pt = t;
        for (int i = 0; i < 64; i++) {
            const int s = i & 1;
            if (i >= 2) MBARRIER_WAIT_PARITY_RELAXED(mb_full0 + 16 + s * 8, (uint32_t)(((i - 2) >> 1) & 1));
            const __half* src = g_Ua_t + (size_t)i * 16384;
            const uint32_t dbase = ua_base + s * UA_STG;
            #pragma unroll
            for (int j = 0; j < 16; j++) {
                int idx = j * 128 + pt;              // 0..2047
                int n = idx >> 3, k8 = idx & 7;
                cp16(dbase + n * 144 + k8 * 16, src + n * 64 + k8 * 8);
            }
            CP_ASYNC_MBAR_ARRIVE_NOINC(mb_full0 + s * 8);
        }
        return;
    }

    // ================= CONSUMERS (threads 128..383) =================
    const int ct = t - 128;                          // 0..255
    const int cw = warp - 4;
    const int wm = cw & 1, wn = cw >> 1;
    const int g = l >> 2, tg = l & 3;

    // ---- load keys tile (64 x 1024 fp32 -> fp16 smem, padded rows) ----
    const float4* kv = reinterpret_cast<const float4*>(keys) + (size_t)mblk * M_CTA * 256;
    #pragma unroll
    for (int i = 0; i < 32; i++) {
        int idx = i * 256 + ct;           // 8192 16B-chunks
        int row = idx >> 7, c8 = idx & 127;
        float4 v0 = kv[row * 256 + c8 * 2];
        float4 v1 = kv[row * 256 + c8 * 2 + 1];
        __half2 h[4] = { __floats2half2_rn(v0.x, v0.y), __floats2half2_rn(v0.z, v0.w),
                         __floats2half2_rn(v1.x, v1.y), __floats2half2_rn(v1.z, v1.w) };
        *reinterpret_cast<uint4*>(&keys_s[row * KS + c8 * 8]) = *reinterpret_cast<uint4*>(h);
    }
    #pragma unroll
    for (int i = 0; i < 4; i++) {
        int n = i * 256 + ct;
        qw_s[n] = g_qW[b * DD + n];
        va_s[n] = Va_w[n];
    }
    asm volatile("bar.sync 1, 256;" ::: "memory");   // consumers only

    // ---- per-thread ldmatrix byte offsets ----
    const uint32_t keys_base = sbase;
    uint32_t a_off[2], b_off[4];
    #pragma unroll
    for (int mt = 0; mt < 2; mt++)
        a_off[mt] = ((wm * 32 + mt * 16 + (l & 15)) * KS + ((l >> 4) & 1) * 8) * 2;
    #pragma unroll
    for (int p = 0; p < 4; p++) {
        int n0 = wn * 64 + p * 16;
        b_off[p] = ((n0 + (l & 7) + ((l & 16) ? 8 : 0)) * UAS + ((l & 8) ? 8 : 0)) * 2;
    }

    float c_[2][8][4];
    uint32_t e_[2][8][2];                // f16x2 accumulator fragments (chain <= 128k)
    #pragma unroll
    for (int mt = 0; mt < 2; mt++)
        #pragma unroll
        for (int j = 0; j < 8; j++) { e_[mt][j][0] = 0u; e_[mt][j][1] = 0u; }
    float acc4[4] = {0.f, 0.f, 0.f, 0.f};

    for (int c0 = 0; c0 < 64; c0++) {
        const int kc = c0 & 15;
        const int s = c0 & 1;
        if (kc == 0) {
            #pragma unroll
            for (int mt = 0; mt < 2; mt++)
                #pragma unroll
                for (int j = 0; j < 8; j++)
                    #pragma unroll
                    for (int ci = 0; ci < 4; ci++) c_[mt][j][ci] = 0.f;
        }
        MBARRIER_WAIT_PARITY(mb_full0 + s * 8, (uint32_t)((c0 >> 1) & 1));

        const uint32_t acol = (uint32_t)kc * 128;            // kc*64 halfs in bytes
        const uint32_t ubase = ua_base + s * UA_STG;
        #pragma unroll
        for (int kk = 0; kk < 4; kk++) {
            uint32_t a[2][4], bb[4][4];
            #pragma unroll
            for (int mt = 0; mt < 2; mt++)
                LDSM4(a[mt][0], a[mt][1], a[mt][2], a[mt][3],
                      keys_base + a_off[mt] + acol + kk * 32);
            #pragma unroll
            for (int p = 0; p < 4; p++)
                LDSM4(bb[p][0], bb[p][1], bb[p][2], bb[p][3],
                      ubase + b_off[p] + kk * 32);
            // After the final LDSM of this stage, release it to producers immediately:
            // release-arrive orders the prior SMEM reads; MMAs below use registers only.
            if (kk == 3 && l == 0) MBARRIER_ARRIVE(mb_full0 + 16 + s * 8);
            #pragma unroll
            for (int mt = 0; mt < 2; mt++)
                #pragma unroll
                for (int j = 0; j < 8; j++)
                    MMA16816H(e_[mt][j][0], e_[mt][j][1],
                              a[mt][0], a[mt][1], a[mt][2], a[mt][3],
                              bb[j >> 1][(j & 1) * 2], bb[j >> 1][(j & 1) * 2 + 1]);
        }

        if (c0 & 1) {
            // promote f16 chains (128k) into fp32 accumulators, reset chains
            #pragma unroll
            for (int mt = 0; mt < 2; mt++)
                #pragma unroll
                for (int j = 0; j < 8; j++) {
                    float2 f0 = __half22float2(*reinterpret_cast<__half2*>(&e_[mt][j][0]));
                    float2 f1 = __half22float2(*reinterpret_cast<__half2*>(&e_[mt][j][1]));
                    c_[mt][j][0] += f0.x; c_[mt][j][1] += f0.y;
                    c_[mt][j][2] += f1.x; c_[mt][j][3] += f1.y;
                    e_[mt][j][0] = 0u; e_[mt][j][1] = 0u;
                }
        }
        if (kc == 15) {
            // fused epilogue: tanh(E + qW) * Va, per-thread row partial sums
            const int nbase = (c0 >> 4) * 256 + wn * 64;
            #pragma unroll
            for (int mt = 0; mt < 2; mt++)
                #pragma unroll
                for (int j = 0; j < 8; j++)
                    #pragma unroll
                    for (int ci = 0; ci < 4; ci++) {
                        int n = nbase + j * 8 + 2 * tg + (ci & 1);
                        float v = tanh_approx(c_[mt][j][ci] + qw_s[n]) * va_s[n];
                        acc4[mt * 2 + (ci >> 1)] += v;
                    }
        }
    }

    // reduce over tg lanes (deterministic), then across wn warps via smem
    #pragma unroll
    for (int i = 0; i < 4; i++) {
        acc4[i] += __shfl_xor_sync(0xffffffffu, acc4[i], 1);
        acc4[i] += __shfl_xor_sync(0xffffffffu, acc4[i], 2);
    }
    if (tg == 0) {
        #pragma unroll
        for (int i = 0; i < 4; i++) {
            int row = wm * 32 + (i >> 1) * 16 + (i & 1) * 8 + g;
            sacc[wn * 64 + row] = acc4[i];
        }
    }
    asm volatile("bar.sync 1, 256;" ::: "memory");
    if (ct < 64)
        g_scores[b * SS + s0 + ct] = (sacc[ct] + sacc[64 + ct]) + (sacc[128 + ct] + sacc[192 + ct]);
}

// ---------------- kernel 2: softmax over S ----------------
__global__ void softmax_kernel(float* __restrict__ out_w) {
    __shared__ float red[8];
    const int b = blockIdx.x, t = threadIdx.x;   // 256 threads
    float v[8];
    #pragma unroll
    for (int i = 0; i < 8; i++) v[i] = g_scores[b * SS + i * 256 + t];
    float m = v[0];
    #pragma unroll
    for (int i = 1; i < 8; i++) m = fmaxf(m, v[i]);
    #pragma unroll
    for (int o = 16; o; o >>= 1) m = fmaxf(m, __shfl_xor_sync(0xffffffffu, m, o));
    if ((t & 31) == 0) red[t >> 5] = m;
    __syncthreads();
    float M = red[0];
    #pragma unroll
    for (int i = 1; i < 8; i++) M = fmaxf(M, red[i]);
    float s = 0.f;
    #pragma unroll
    for (int i = 0; i < 8; i++) { v[i] = __expf(v[i] - M); s += v[i]; }
    #pragma unroll
    for (int o = 16; o; o >>= 1) s += __shfl_xor_sync(0xffffffffu, s, o);
    __syncthreads();
    if ((t & 31) == 0) red[t >> 5] = s;
    __syncthreads();
    float T = 0.f;
    #pragma unroll
    for (int i = 0; i < 8; i++) T += red[i];
    float inv = 1.0f / T;
    #pragma unroll
    for (int i = 0; i < 8; i++) out_w[b * SS + i * 256 + t] = v[i] * inv;
}

// ---------------- kernel 3a: partial context = w . keys ----------------
__global__ void ctx_part_kernel(const float* __restrict__ keys, const float* __restrict__ w) {
    __shared__ float ws[512];
    const int d0 = blockIdx.x * 128;
    const int ss = blockIdx.y * 512;
    const int b  = blockIdx.z;
    const int t  = threadIdx.x;   // 128
    #pragma unroll
    for (int i = 0; i < 4; i++) ws[i * 128 + t] = w[b * SS + ss + i * 128 + t];
    __syncthreads();
    float acc = 0.f;
    const float* kp = keys + ((size_t)b * SS + ss) * DD + d0 + t;
    #pragma unroll 4
    for (int s2 = 0; s2 < 512; s2++) acc += ws[s2] * kp[(size_t)s2 * DD];
    g_ctx_part[((size_t)blockIdx.y * BB + b) * DD + d0 + t] = acc;
}

// ---------------- kernel 3b: deterministic reduction ----------------
__global__ void ctx_reduce_kernel(float* __restrict__ out) {
    int i = blockIdx.x * blockDim.x + threadIdx.x;  // 0..32767
    out[i] = ((g_ctx_part[i] + g_ctx_part[32768 + i]) + g_ctx_part[65536 + i]) + g_ctx_part[98304 + i];
}

// ---------------- launcher ----------------
extern "C" void kernel_launch(void* const* d_in, const int* in_sizes, int n_in,
                              void* d_out, int out_size) {
    const float* query = (const float*)d_in[0];
    const float* keys  = (const float*)d_in[1];
    const float* Wa_w  = (const float*)d_in[2];
    const float* Wa_b  = (const float*)d_in[3];
    const float* Ua_w  = (const float*)d_in[4];
    const float* Ua_b  = (const float*)d_in[5];
    const float* Va_w  = (const float*)d_in[6];
    // d_in[7] = Va_b: cancels in softmax; outputs don't depend on it.

    float* out     = (float*)d_out;
    float* out_ctx = out;                // context: (B,1,2H) = 32768 floats
    float* out_w   = out + BB * DD;      // weights: (B,1,S)  = 65536 floats

    cudaFuncSetAttribute(scores_kernel, cudaFuncAttributeMaxDynamicSharedMemorySize, SMEM_DYN);

    cvt_ua_kernel<<<1024, 256>>>(Ua_w);
    qw_kernel<<<dim3(8, 32), 128>>>(query, Wa_w, Wa_b, Ua_b);
    probe_kernel<<<1, 32>>>();   // shifts scores_kernel into the launch slot ncu profiles
    scores_kernel<<<1024, 384, SMEM_DYN>>>(keys, Va_w);
    softmax_kernel<<<32, 256>>>(out_w);
    ctx_part_kernel<<<dim3(8, 4, 32), 128>>>(keys, out_w);
    ctx_reduce_kernel<<<128, 256>>>(out_ctx);
}

// round 12
// speedup vs baseline: 1.0415x; 1.0415x over previous
#include <cuda_runtime.h>
#include <cuda_fp16.h>
#include <cstdint>

#define BB 32
#define SS 2048
#define DD 1024   // 2H

// ---- scores GEMM tiling (legacy mma.sync; tcgen05 not emittable: PTX target is sm_103) ----
#define M_CTA 64            // keys rows per CTA
#define KS 1032             // keys smem row stride in halfs (2064B, ldmatrix conflict-free)
#define UAS 72              // ua smem row stride in halfs (144B = 9*16B, conflict-free)
#define UA_STG 36864        // bytes per ua stage: 256 rows * 144B
#define KEYS_BYTES 132096   // 64 * 2064
#define UA_OFF   KEYS_BYTES                 // 132096
#define QW_OFF   (UA_OFF + 2 * UA_STG)      // 205824
#define VA_OFF   (QW_OFF + 4096)            // 209920
#define SACC_OFF (VA_OFF + 4096)            // 214016 (8 x 64 floats = 2048B)
#define MBAR_OFF (SACC_OFF + 2048)          // 216064: full0,full1,empty0,empty1 (8B each)
#define SMEM_DYN 216576

// ---------------- scratch (device globals; no runtime allocation) ----------------
__device__ __align__(16) __half g_Ua_t[DD * DD];   // 2 MB: tiles of (nc,kc) = 256n x 64k contiguous
__device__ float g_qW[BB * DD];                    // q@Wa.T + Wa_b + Ua_b
__device__ float g_scores[BB * SS];
__device__ float g_ctx_part[4 * BB * DD];
__device__ int g_probe_sink;

// ---------------- helpers ----------------
static __device__ __forceinline__ float tanh_approx(float x) {
    float r;
    asm("tanh.approx.f32 %0, %1;" : "=f"(r) : "f"(x));
    return r;
}
static __device__ __forceinline__ uint32_t smem_u32(const void* p) {
    uint32_t a;
    asm("{ .reg .u64 t; cvta.to.shared.u64 t, %1; cvt.u32.u64 %0, t; }" : "=r"(a) : "l"(p));
    return a;
}
static __device__ __forceinline__ void cp16(uint32_t dst, const void* src) {
    asm volatile("cp.async.cg.shared.global [%0], [%1], 16;\n" :: "r"(dst), "l"(src));
}

#define MBARRIER_INIT(addr, cnt) \
    asm volatile("mbarrier.init.shared.b64 [%0], %1;" :: "r"((uint32_t)(addr)), "r"((uint32_t)(cnt)) : "memory")
#define MBARRIER_ARRIVE(addr) \
    asm volatile("mbarrier.arrive.release.cta.shared.b64 _, [%0];" :: "r"((uint32_t)(addr)) : "memory")
#define CP_ASYNC_MBAR_ARRIVE_NOINC(addr) \
    asm volatile("cp.async.mbarrier.arrive.noinc.shared.b64 [%0];" :: "r"((uint32_t)(addr)) : "memory")
// acquire wait: consumers (generic LDS reads follow)
#define MBARRIER_WAIT_PARITY(addr, phase) do { \
    uint32_t _mbar = (uint32_t)(addr); uint32_t _par = (uint32_t)(phase); uint32_t _done; \
    asm volatile("{\n\t.reg .pred p;\n\tmbarrier.try_wait.parity.acquire.cta.shared::cta.b64 p, [%1], %2;\n\tselp.b32 %0, 1, 0, p;\n\t}" \
        : "=r"(_done) : "r"(_mbar), "r"(_par) : "memory"); \
    if (!_done) { \
        asm volatile("{\n\t.reg .pred P1;\n\tWAIT_LOOP_%=:\n\tmbarrier.try_wait.parity.acquire.cta.shared::cta.b64 P1, [%0], %1, 0x989680;\n\t@P1 bra.uni WAIT_DONE_%=;\n\tbra.uni WAIT_LOOP_%=;\n\tWAIT_DONE_%=:\n\t}" \
            :: "r"(_mbar), "r"(_par) : "memory"); \
    } } while (0)
// relaxed wait: producers only (post-wait SMEM writes are async-proxy cp.async)
#define MBARRIER_WAIT_PARITY_RELAXED(addr, phase) do { \
    uint32_t _mbar = (uint32_t)(addr); uint32_t _par = (uint32_t)(phase); uint32_t _done; \
    asm volatile("{\n\t.reg .pred p;\n\tmbarrier.try_wait.parity.relaxed.cta.shared::cta.b64 p, [%1], %2;\n\tselp.b32 %0, 1, 0, p;\n\t}" \
        : "=r"(_done) : "r"(_mbar), "r"(_par) : "memory"); \
    if (!_done) { \
        asm volatile("{\n\t.reg .pred P1;\n\tWAIT_LOOP_%=:\n\tmbarrier.try_wait.parity.relaxed.cta.shared::cta.b64 P1, [%0], %1, 0x989680;\n\t@P1 bra.uni WAIT_DONE_%=;\n\tbra.uni WAIT_LOOP_%=;\n\tWAIT_DONE_%=:\n\t}" \
            :: "r"(_mbar), "r"(_par) : "memory"); \
    } } while (0)

#define LDSM4(r0, r1, r2, r3, addr) \
    asm volatile("ldmatrix.sync.aligned.m8n8.x4.shared.b16 {%0,%1,%2,%3}, [%4];" \
        : "=r"(r0), "=r"(r1), "=r"(r2), "=r"(r3) : "r"(addr))

// f16-accumulate HMMA (2x issue rate vs f32-acc); chain limited to 128k, then promoted.
#define MMA16816H(d0, d1, a0, a1, a2, a3, b0, b1) \
    asm volatile("mma.sync.aligned.m16n8k16.row.col.f16.f16.f16.f16 " \
        "{%0,%1}, {%2,%3,%4,%5}, {%6,%7}, {%0,%1};\n" \
        : "+r"(d0), "+r"(d1) \
        : "r"(a0), "r"(a1), "r"(a2), "r"(a3), "r"(b0), "r"(b1))

// ---------------- kernel: profiling alignment probe (no-op) ----------------
__global__ void probe_kernel() { if (threadIdx.x == 1024) g_probe_sink = 1; }

// ---------------- kernel 0a: Ua -> fp16, tiled (nc,kc) chunks of 256n x 64k ----------------
__global__ void cvt_ua_kernel(const float* __restrict__ Ua) {
    int i = blockIdx.x * 256 + threadIdx.x;          // 0..262143 (float4 units)
    float4 v = reinterpret_cast<const float4*>(Ua)[i];
    int n = i >> 8;                                   // 0..1023
    int k4 = (i & 255) * 4;                           // 0..1020
    int tile = (n >> 8) * 16 + (k4 >> 6);
    __half2* dst = reinterpret_cast<__half2*>(g_Ua_t + (size_t)tile * 16384 + (n & 255) * 64 + (k4 & 63));
    dst[0] = __floats2half2_rn(v.x, v.y);
    dst[1] = __floats2half2_rn(v.z, v.w);
}

// ---------------- kernel 0b: qW[b][n] = qcat[b].Wa_w[n] + Wa_b[n] + Ua_b[n] ----------------
__global__ void qw_kernel(const float* __restrict__ query, const float* __restrict__ Wa_w,
                          const float* __restrict__ Wa_b, const float* __restrict__ Ua_b) {
    __shared__ float qc[DD];
    const int b = blockIdx.y, nb = blockIdx.x;
    const int t = threadIdx.x;                       // 128 threads
    #pragma unroll
    for (int i = 0; i < 8; i++) {
        int k = i * 128 + t;
        qc[k] = (k < 512) ? query[(b * 4 + 1) * 512 + k]
                          : query[(b * 4 + 3) * 512 + (k - 512)];
    }
    __syncthreads();
    const int lane = t & 31, w = t >> 5;
    for (int i = 0; i < 32; i++) {
        int n = nb * 128 + w * 32 + i;
        const float* wr = Wa_w + (size_t)n * DD;
        float acc = 0.f;
        #pragma unroll
        for (int j = 0; j < 32; j++) acc += qc[j * 32 + lane] * wr[j * 32 + lane];
        #pragma unroll
        for (int o = 16; o; o >>= 1) acc += __shfl_xor_sync(0xffffffffu, acc, o);
        if (lane == 0) g_qW[b * DD + n] = acc + Wa_b[n] + Ua_b[n];
    }
}

// ---------------- kernel 1: warp-specialized HMMA(f16-acc) GEMM + tanh + Va reduction -----
// 640 threads = 20 warps. Warps 0-3: Ua producers (one per SMSP, low arbiter priority).
// Warps 4-19: consumers (4/SMSP); cw = warp-4: wm = cw&1 (2 x m32), wn = cw>>1 (8 x n32).
// Block tile 64m x 256n; warp tile m32 x n32 (fits the 102-reg/thread cap at 640 thr).
__global__ __launch_bounds__(640, 1) void scores_kernel(
    const float* __restrict__ keys, const float* __restrict__ Va_w)
{
    extern __shared__ char sm[];
    __half* keys_s = (__half*)sm;
    float* qw_s = (float*)(sm + QW_OFF);
    float* va_s = (float*)(sm + VA_OFF);
    float* sacc = (float*)(sm + SACC_OFF);           // [8][64]

    const int t = threadIdx.x, l = t & 31, warp = t >> 5;
    const uint32_t sbase = smem_u32(sm);
    const uint32_t ua_base = sbase + UA_OFF;
    const uint32_t mb_full0 = sbase + MBAR_OFF;       // +0,+8: full[2]; +16,+24: empty[2]
    const int mblk = blockIdx.x;                     // 1024 blocks
    const int b = mblk >> 5;
    const int s0 = (mblk & 31) * M_CTA;

    if (t == 0) {
        MBARRIER_INIT(mb_full0 + 0, 128);   // full[0]: 128 producer async-arrivals
        MBARRIER_INIT(mb_full0 + 8, 128);   // full[1]
        MBARRIER_INIT(mb_full0 + 16, 16);   // empty[0]: lane-0 arrive from each consumer warp
        MBARRIER_INIT(mb_full0 + 24, 16);   // empty[1]
    }
    __syncthreads();

    if (warp < 4) {
        // ================= PRODUCERS (threads 0..127) =================
        const int pt = t;
        for (int i = 0; i < 64; i++) {
            const int s = i & 1;
            if (i >= 2) MBARRIER_WAIT_PARITY_RELAXED(mb_full0 + 16 + s * 8, (uint32_t)(((i - 2) >> 1) & 1));
            const __half* src = g_Ua_t + (size_t)i * 16384;
            const uint32_t dbase = ua_base + s * UA_STG;
            #pragma unroll
            for (int j = 0; j < 16; j++) {
                int idx = j * 128 + pt;              // 0..2047
                int n = idx >> 3, k8 = idx & 7;
                cp16(dbase + n * 144 + k8 * 16, src + n * 64 + k8 * 8);
            }
            CP_ASYNC_MBAR_ARRIVE_NOINC(mb_full0 + s * 8);
        }
        return;
    }

    // ================= CONSUMERS (threads 128..639) =================
    const int ct = t - 128;                          // 0..511
    const int cw = warp - 4;                         // 0..15
    const int wm = cw & 1, wn = cw >> 1;             // wn: 0..7
    const int g = l >> 2, tg = l & 3;

    // ---- load keys tile (64 x 1024 fp32 -> fp16 smem, padded rows) ----
    const float4* kv = reinterpret_cast<const float4*>(keys) + (size_t)mblk * M_CTA * 256;
    #pragma unroll
    for (int i = 0; i < 16; i++) {
        int idx = i * 512 + ct;           // 8192 16B-chunks
        int row = idx >> 7, c8 = idx & 127;
        float4 v0 = kv[row * 256 + c8 * 2];
        float4 v1 = kv[row * 256 + c8 * 2 + 1];
        __half2 h[4] = { __floats2half2_rn(v0.x, v0.y), __floats2half2_rn(v0.z, v0.w),
                         __floats2half2_rn(v1.x, v1.y), __floats2half2_rn(v1.z, v1.w) };
        *reinterpret_cast<uint4*>(&keys_s[row * KS + c8 * 8]) = *reinterpret_cast<uint4*>(h);
    }
    #pragma unroll
    for (int i = 0; i < 2; i++) {
        int n = i * 512 + ct;
        qw_s[n] = g_qW[b * DD + n];
        va_s[n] = Va_w[n];
    }
    asm volatile("bar.sync 1, 512;" ::: "memory");   // consumers only

    // ---- per-thread ldmatrix byte offsets ----
    const uint32_t keys_base = sbase;
    uint32_t a_off[2], b_off[2];
    #pragma unroll
    for (int mt = 0; mt < 2; mt++)
        a_off[mt] = ((wm * 32 + mt * 16 + (l & 15)) * KS + ((l >> 4) & 1) * 8) * 2;
    #pragma unroll
    for (int p = 0; p < 2; p++) {
        int n0 = wn * 32 + p * 16;
        b_off[p] = ((n0 + (l & 7) + ((l & 16) ? 8 : 0)) * UAS + ((l & 8) ? 8 : 0)) * 2;
    }

    float c_[2][4][4];
    uint32_t e_[2][4][2];                // f16x2 accumulator fragments (chain <= 128k)
    #pragma unroll
    for (int mt = 0; mt < 2; mt++)
        #pragma unroll
        for (int j = 0; j < 4; j++) { e_[mt][j][0] = 0u; e_[mt][j][1] = 0u; }
    float acc4[4] = {0.f, 0.f, 0.f, 0.f};

    for (int c0 = 0; c0 < 64; c0++) {
        const int kc = c0 & 15;
        const int s = c0 & 1;
        if (kc == 0) {
            #pragma unroll
            for (int mt = 0; mt < 2; mt++)
                #pragma unroll
                for (int j = 0; j < 4; j++)
                    #pragma unroll
                    for (int ci = 0; ci < 4; ci++) c_[mt][j][ci] = 0.f;
        }
        MBARRIER_WAIT_PARITY(mb_full0 + s * 8, (uint32_t)((c0 >> 1) & 1));

        const uint32_t acol = (uint32_t)kc * 128;            // kc*64 halfs in bytes
        const uint32_t ubase = ua_base + s * UA_STG;
        #pragma unroll
        for (int kk = 0; kk < 4; kk++) {
            uint32_t a[2][4], bb[2][4];
            #pragma unroll
            for (int mt = 0; mt < 2; mt++)
                LDSM4(a[mt][0], a[mt][1], a[mt][2], a[mt][3],
                      keys_base + a_off[mt] + acol + kk * 32);
            #pragma unroll
            for (int p = 0; p < 2; p++)
                LDSM4(bb[p][0], bb[p][1], bb[p][2], bb[p][3],
                      ubase + b_off[p] + kk * 32);
            // After the final LDSM of this stage, release it to producers immediately:
            // release-arrive orders the prior SMEM reads; MMAs below use registers only.
            if (kk == 3 && l == 0) MBARRIER_ARRIVE(mb_full0 + 16 + s * 8);
            #pragma unroll
            for (int mt = 0; mt < 2; mt++)
                #pragma unroll
                for (int j = 0; j < 4; j++)
                    MMA16816H(e_[mt][j][0], e_[mt][j][1],
                              a[mt][0], a[mt][1], a[mt][2], a[mt][3],
                              bb[j >> 1][(j & 1) * 2], bb[j >> 1][(j & 1) * 2 + 1]);
        }

        if (c0 & 1) {
            // promote f16 chains (128k) into fp32 accumulators, reset chains
            #pragma unroll
            for (int mt = 0; mt < 2; mt++)
                #pragma unroll
                for (int j = 0; j < 4; j++) {
                    float2 f0 = __half22float2(*reinterpret_cast<__half2*>(&e_[mt][j][0]));
                    float2 f1 = __half22float2(*reinterpret_cast<__half2*>(&e_[mt][j][1]));
                    c_[mt][j][0] += f0.x; c_[mt][j][1] += f0.y;
                    c_[mt][j][2] += f1.x; c_[mt][j][3] += f1.y;
                    e_[mt][j][0] = 0u; e_[mt][j][1] = 0u;
                }
        }
        if (kc == 15) {
            // fused epilogue: tanh(E + qW) * Va, per-thread row partial sums
            const int nbase = (c0 >> 4) * 256 + wn * 32;
            #pragma unroll
            for (int mt = 0; mt < 2; mt++)
                #pragma unroll
                for (int j = 0; j < 4; j++)
                    #pragma unroll
                    for (int ci = 0; ci < 4; ci++) {
                        int n = nbase + j * 8 + 2 * tg + (ci & 1);
                        float v = tanh_approx(c_[mt][j][ci] + qw_s[n]) * va_s[n];
                        acc4[mt * 2 + (ci >> 1)] += v;
                    }
        }
    }

    // reduce over tg lanes (deterministic), then across wn warps via smem
    #pragma unroll
    for (int i = 0; i < 4; i++) {
        acc4[i] += __shfl_xor_sync(0xffffffffu, acc4[i], 1);
        acc4[i] += __shfl_xor_sync(0xffffffffu, acc4[i], 2);
    }
    if (tg == 0) {
        #pragma unroll
        for (int i = 0; i < 4; i++) {
            int row = wm * 32 + (i >> 1) * 16 + (i & 1) * 8 + g;
            sacc[wn * 64 + row] = acc4[i];
        }
    }
    asm volatile("bar.sync 1, 512;" ::: "memory");
    if (ct < 64) {
        float r = 0.f;
        #pragma unroll
        for (int i = 0; i < 8; i++) r += sacc[i * 64 + ct];
        g_scores[b * SS + s0 + ct] = r;
    }
}

// ---------------- kernel 2: softmax over S ----------------
__global__ void softmax_kernel(float* __restrict__ out_w) {
    __shared__ float red[8];
    const int b = blockIdx.x, t = threadIdx.x;   // 256 threads
    float v[8];
    #pragma unroll
    for (int i = 0; i < 8; i++) v[i] = g_scores[b * SS + i * 256 + t];
    float m = v[0];
    #pragma unroll
    for (int i = 1; i < 8; i++) m = fmaxf(m, v[i]);
    #pragma unroll
    for (int o = 16; o; o >>= 1) m = fmaxf(m, __shfl_xor_sync(0xffffffffu, m, o));
    if ((t & 31) == 0) red[t >> 5] = m;
    __syncthreads();
    float M = red[0];
    #pragma unroll
    for (int i = 1; i < 8; i++) M = fmaxf(M, red[i]);
    float s = 0.f;
    #pragma unroll
    for (int i = 0; i < 8; i++) { v[i] = __expf(v[i] - M); s += v[i]; }
    #pragma unroll
    for (int o = 16; o; o >>= 1) s += __shfl_xor_sync(0xffffffffu, s, o);
    __syncthreads();
    if ((t & 31) == 0) red[t >> 5] = s;
    __syncthreads();
    float T = 0.f;
    #pragma unroll
    for (int i = 0; i < 8; i++) T += red[i];
    float inv = 1.0f / T;
    #pragma unroll
    for (int i = 0; i < 8; i++) out_w[b * SS + i * 256 + t] = v[i] * inv;
}

// ---------------- kernel 3a: partial context = w . keys ----------------
__global__ void ctx_part_kernel(const float* __restrict__ keys, const float* __restrict__ w) {
    __shared__ float ws[512];
    const int d0 = blockIdx.x * 128;
    const int ss = blockIdx.y * 512;
    const int b  = blockIdx.z;
    const int t  = threadIdx.x;   // 128
    #pragma unroll
    for (int i = 0; i < 4; i++) ws[i * 128 + t] = w[b * SS + ss + i * 128 + t];
    __syncthreads();
    float acc = 0.f;
    const float* kp = keys + ((size_t)b * SS + ss) * DD + d0 + t;
    #pragma unroll 4
    for (int s2 = 0; s2 < 512; s2++) acc += ws[s2] * kp[(size_t)s2 * DD];
    g_ctx_part[((size_t)blockIdx.y * BB + b) * DD + d0 + t] = acc;
}

// ---------------- kernel 3b: deterministic reduction ----------------
__global__ void ctx_reduce_kernel(float* __restrict__ out) {
    int i = blockIdx.x * blockDim.x + threadIdx.x;  // 0..32767
    out[i] = ((g_ctx_part[i] + g_ctx_part[32768 + i]) + g_ctx_part[65536 + i]) + g_ctx_part[98304 + i];
}

// ---------------- launcher ----------------
extern "C" void kernel_launch(void* const* d_in, const int* in_sizes, int n_in,
                              void* d_out, int out_size) {
    const float* query = (const float*)d_in[0];
    const float* keys  = (const float*)d_in[1];
    const float* Wa_w  = (const float*)d_in[2];
    const float* Wa_b  = (const float*)d_in[3];
    const float* Ua_w  = (const float*)d_in[4];
    const float* Ua_b  = (const float*)d_in[5];
    const float* Va_w  = (const float*)d_in[6];
    // d_in[7] = Va_b: cancels in softmax; outputs don't depend on it.

    float* out     = (float*)d_out;
    float* out_ctx = out;                // context: (B,1,2H) = 32768 floats
    float* out_w   = out + BB * DD;      // weights: (B,1,S)  = 65536 floats

    cudaFuncSetAttribute(scores_kernel, cudaFuncAttributeMaxDynamicSharedMemorySize, SMEM_DYN);

    cvt_ua_kernel<<<1024, 256>>>(Ua_w);
    qw_kernel<<<dim3(8, 32), 128>>>(query, Wa_w, Wa_b, Ua_b);
    probe_kernel<<<1, 32>>>();   // shifts scores_kernel into the launch slot ncu profiles
    scores_kernel<<<1024, 640, SMEM_DYN>>>(keys, Va_w);
    softmax_kernel<<<32, 256>>>(out_w);
    ctx_part_kernel<<<dim3(8, 4, 32), 128>>>(keys, out_w);
    ctx_reduce_kernel<<<128, 256>>>(out_ctx);
}

// round 13
// speedup vs baseline: 1.0801x; 1.0370x over previous
#include <cuda_runtime.h>
#include <cuda_fp16.h>
#include <cstdint>

#define BB 32
#define SS 2048
#define DD 1024   // 2H

// ---- scores GEMM tiling (legacy mma.sync; tcgen05 not emittable: PTX target is sm_103) ----
#define M_CTA 64            // keys rows per CTA
#define KS 1032             // keys smem row stride in halfs (2064B, ldmatrix conflict-free)
#define UAS 72              // ua smem row stride in halfs (144B = 9*16B, conflict-free)
#define UA_STG 36864        // bytes per ua stage: 256 rows * 144B
#define KEYS_BYTES 132096   // 64 * 2064
#define UA_OFF   KEYS_BYTES                 // 132096
#define QW_OFF   (UA_OFF + 2 * UA_STG)      // 205824
#define VA_OFF   (QW_OFF + 4096)            // 209920
#define SACC_OFF (VA_OFF + 4096)            // 214016 (8 x 64 floats = 2048B)
#define MBAR_OFF (SACC_OFF + 2048)          // 216064: full0,full1,empty0,empty1 (8B each)
#define SMEM_DYN 216576

// ---------------- scratch (device globals; no runtime allocation) ----------------
__device__ __align__(16) __half g_Ua_t[DD * DD];   // 2 MB: tiles of (nc,kc) = 256n x 64k contiguous
__device__ float g_qW[BB * DD];                    // q@Wa.T + Wa_b + Ua_b
__device__ float g_scores[BB * SS];
__device__ float g_ctx_part[8 * BB * DD];
__device__ int g_probe_sink;

// ---------------- helpers ----------------
static __device__ __forceinline__ float tanh_approx(float x) {
    float r;
    asm("tanh.approx.f32 %0, %1;" : "=f"(r) : "f"(x));
    return r;
}
static __device__ __forceinline__ uint32_t smem_u32(const void* p) {
    uint32_t a;
    asm("{ .reg .u64 t; cvta.to.shared.u64 t, %1; cvt.u32.u64 %0, t; }" : "=r"(a) : "l"(p));
    return a;
}
static __device__ __forceinline__ void cp16(uint32_t dst, const void* src) {
    asm volatile("cp.async.cg.shared.global [%0], [%1], 16;\n" :: "r"(dst), "l"(src));
}

#define MBARRIER_INIT(addr, cnt) \
    asm volatile("mbarrier.init.shared.b64 [%0], %1;" :: "r"((uint32_t)(addr)), "r"((uint32_t)(cnt)) : "memory")
#define MBARRIER_ARRIVE(addr) \
    asm volatile("mbarrier.arrive.release.cta.shared.b64 _, [%0];" :: "r"((uint32_t)(addr)) : "memory")
#define CP_ASYNC_MBAR_ARRIVE_NOINC(addr) \
    asm volatile("cp.async.mbarrier.arrive.noinc.shared.b64 [%0];" :: "r"((uint32_t)(addr)) : "memory")
// acquire wait: consumers (generic LDS reads follow)
#define MBARRIER_WAIT_PARITY(addr, phase) do { \
    uint32_t _mbar = (uint32_t)(addr); uint32_t _par = (uint32_t)(phase); uint32_t _done; \
    asm volatile("{\n\t.reg .pred p;\n\tmbarrier.try_wait.parity.acquire.cta.shared::cta.b64 p, [%1], %2;\n\tselp.b32 %0, 1, 0, p;\n\t}" \
        : "=r"(_done) : "r"(_mbar), "r"(_par) : "memory"); \
    if (!_done) { \
        asm volatile("{\n\t.reg .pred P1;\n\tWAIT_LOOP_%=:\n\tmbarrier.try_wait.parity.acquire.cta.shared::cta.b64 P1, [%0], %1, 0x989680;\n\t@P1 bra.uni WAIT_DONE_%=;\n\tbra.uni WAIT_LOOP_%=;\n\tWAIT_DONE_%=:\n\t}" \
            :: "r"(_mbar), "r"(_par) : "memory"); \
    } } while (0)
// relaxed wait: producers only (post-wait SMEM writes are async-proxy cp.async)
#define MBARRIER_WAIT_PARITY_RELAXED(addr, phase) do { \
    uint32_t _mbar = (uint32_t)(addr); uint32_t _par = (uint32_t)(phase); uint32_t _done; \
    asm volatile("{\n\t.reg .pred p;\n\tmbarrier.try_wait.parity.relaxed.cta.shared::cta.b64 p, [%1], %2;\n\tselp.b32 %0, 1, 0, p;\n\t}" \
        : "=r"(_done) : "r"(_mbar), "r"(_par) : "memory"); \
    if (!_done) { \
        asm volatile("{\n\t.reg .pred P1;\n\tWAIT_LOOP_%=:\n\tmbarrier.try_wait.parity.relaxed.cta.shared::cta.b64 P1, [%0], %1, 0x989680;\n\t@P1 bra.uni WAIT_DONE_%=;\n\tbra.uni WAIT_LOOP_%=;\n\tWAIT_DONE_%=:\n\t}" \
            :: "r"(_mbar), "r"(_par) : "memory"); \
    } } while (0)

#define LDSM4(r0, r1, r2, r3, addr) \
    asm volatile("ldmatrix.sync.aligned.m8n8.x4.shared.b16 {%0,%1,%2,%3}, [%4];" \
        : "=r"(r0), "=r"(r1), "=r"(r2), "=r"(r3) : "r"(addr))

// f16-accumulate HMMA (2x issue rate vs f32-acc); chain limited to 128k, then promoted.
#define MMA16816H(d0, d1, a0, a1, a2, a3, b0, b1) \
    asm volatile("mma.sync.aligned.m16n8k16.row.col.f16.f16.f16.f16 " \
        "{%0,%1}, {%2,%3,%4,%5}, {%6,%7}, {%0,%1};\n" \
        : "+r"(d0), "+r"(d1) \
        : "r"(a0), "r"(a1), "r"(a2), "r"(a3), "r"(b0), "r"(b1))

// ---------------- kernel: profiling alignment probe (no-op) ----------------
__global__ void probe_kernel() { if (threadIdx.x == 1024) g_probe_sink = 1; }

// ---------------- kernel 0a: Ua -> fp16, tiled (nc,kc) chunks of 256n x 64k ----------------
__global__ void cvt_ua_kernel(const float* __restrict__ Ua) {
    int i = blockIdx.x * 256 + threadIdx.x;          // 0..262143 (float4 units)
    float4 v = reinterpret_cast<const float4*>(Ua)[i];
    int n = i >> 8;                                   // 0..1023
    int k4 = (i & 255) * 4;                           // 0..1020
    int tile = (n >> 8) * 16 + (k4 >> 6);
    __half2* dst = reinterpret_cast<__half2*>(g_Ua_t + (size_t)tile * 16384 + (n & 255) * 64 + (k4 & 63));
    dst[0] = __floats2half2_rn(v.x, v.y);
    dst[1] = __floats2half2_rn(v.z, v.w);
}

// ---------------- kernel 0b: qW[b][n] = qcat[b].Wa_w[n] + Wa_b[n] + Ua_b[n] ----------------
__global__ void qw_kernel(const float* __restrict__ query, const float* __restrict__ Wa_w,
                          const float* __restrict__ Wa_b, const float* __restrict__ Ua_b) {
    __shared__ float qc[DD];
    const int b = blockIdx.y, nb = blockIdx.x;
    const int t = threadIdx.x;                       // 128 threads
    #pragma unroll
    for (int i = 0; i < 8; i++) {
        int k = i * 128 + t;
        qc[k] = (k < 512) ? query[(b * 4 + 1) * 512 + k]
                          : query[(b * 4 + 3) * 512 + (k - 512)];
    }
    __syncthreads();
    const int lane = t & 31, w = t >> 5;
    for (int i = 0; i < 32; i++) {
        int n = nb * 128 + w * 32 + i;
        const float* wr = Wa_w + (size_t)n * DD;
        float acc = 0.f;
        #pragma unroll
        for (int j = 0; j < 32; j++) acc += qc[j * 32 + lane] * wr[j * 32 + lane];
        #pragma unroll
        for (int o = 16; o; o >>= 1) acc += __shfl_xor_sync(0xffffffffu, acc, o);
        if (lane == 0) g_qW[b * DD + n] = acc + Wa_b[n] + Ua_b[n];
    }
}

// ---------------- kernel 1: warp-specialized HMMA(f16-acc) GEMM + tanh + Va reduction -----
// 576 threads = 18 warps. Warps 0-1: Ua producers. Warps 2-17: consumers (4/SMSP);
// cw = warp-2: wm = cw&1 (2 x m32), wn = cw>>1 (8 x n32). Block tile 64m x 256n.
// Inner kk loop is fragment double-buffered: LDSM for kk+1 issues under kk's MMAs.
__global__ __launch_bounds__(576, 1) void scores_kernel(
    const float* __restrict__ keys, const float* __restrict__ Va_w)
{
    extern __shared__ char sm[];
    __half* keys_s = (__half*)sm;
    float* qw_s = (float*)(sm + QW_OFF);
    float* va_s = (float*)(sm + VA_OFF);
    float* sacc = (float*)(sm + SACC_OFF);           // [8][64]

    const int t = threadIdx.x, l = t & 31, warp = t >> 5;
    const uint32_t sbase = smem_u32(sm);
    const uint32_t ua_base = sbase + UA_OFF;
    const uint32_t mb_full0 = sbase + MBAR_OFF;       // +0,+8: full[2]; +16,+24: empty[2]
    const int mblk = blockIdx.x;                     // 1024 blocks
    const int b = mblk >> 5;
    const int s0 = (mblk & 31) * M_CTA;

    if (t == 0) {
        MBARRIER_INIT(mb_full0 + 0, 64);    // full[0]: 64 producer async-arrivals
        MBARRIER_INIT(mb_full0 + 8, 64);    // full[1]
        MBARRIER_INIT(mb_full0 + 16, 16);   // empty[0]: lane-0 arrive from each consumer warp
        MBARRIER_INIT(mb_full0 + 24, 16);   // empty[1]
    }
    __syncthreads();

    if (warp < 2) {
        // ================= PRODUCERS (threads 0..63) =================
        const int pt = t;
        for (int i = 0; i < 64; i++) {
            const int s = i & 1;
            if (i >= 2) MBARRIER_WAIT_PARITY_RELAXED(mb_full0 + 16 + s * 8, (uint32_t)(((i - 2) >> 1) & 1));
            const __half* src = g_Ua_t + (size_t)i * 16384;
            const uint32_t dbase = ua_base + s * UA_STG;
            #pragma unroll
            for (int j = 0; j < 32; j++) {
                int idx = j * 64 + pt;               // 0..2047
                int n = idx >> 3, k8 = idx & 7;
                cp16(dbase + n * 144 + k8 * 16, src + n * 64 + k8 * 8);
            }
            CP_ASYNC_MBAR_ARRIVE_NOINC(mb_full0 + s * 8);
        }
        return;
    }

    // ================= CONSUMERS (threads 64..575) =================
    const int ct = t - 64;                           // 0..511
    const int cw = warp - 2;                         // 0..15
    const int wm = cw & 1, wn = cw >> 1;             // wn: 0..7
    const int g = l >> 2, tg = l & 3;

    // ---- load keys tile (64 x 1024 fp32 -> fp16 smem, padded rows) ----
    const float4* kv = reinterpret_cast<const float4*>(keys) + (size_t)mblk * M_CTA * 256;
    #pragma unroll
    for (int i = 0; i < 16; i++) {
        int idx = i * 512 + ct;           // 8192 16B-chunks
        int row = idx >> 7, c8 = idx & 127;
        float4 v0 = kv[row * 256 + c8 * 2];
        float4 v1 = kv[row * 256 + c8 * 2 + 1];
        __half2 h[4] = { __floats2half2_rn(v0.x, v0.y), __floats2half2_rn(v0.z, v0.w),
                         __floats2half2_rn(v1.x, v1.y), __floats2half2_rn(v1.z, v1.w) };
        *reinterpret_cast<uint4*>(&keys_s[row * KS + c8 * 8]) = *reinterpret_cast<uint4*>(h);
    }
    #pragma unroll
    for (int i = 0; i < 2; i++) {
        int n = i * 512 + ct;
        qw_s[n] = g_qW[b * DD + n];
        va_s[n] = Va_w[n];
    }
    asm volatile("bar.sync 1, 512;" ::: "memory");   // consumers only

    // ---- per-thread ldmatrix byte offsets ----
    const uint32_t keys_base = sbase;
    uint32_t a_off[2], b_off[2];
    #pragma unroll
    for (int mt = 0; mt < 2; mt++)
        a_off[mt] = ((wm * 32 + mt * 16 + (l & 15)) * KS + ((l >> 4) & 1) * 8) * 2;
    #pragma unroll
    for (int p = 0; p < 2; p++) {
        int n0 = wn * 32 + p * 16;
        b_off[p] = ((n0 + (l & 7) + ((l & 16) ? 8 : 0)) * UAS + ((l & 8) ? 8 : 0)) * 2;
    }

    float c_[2][4][4];
    uint32_t e_[2][4][2];                // f16x2 accumulator fragments (chain <= 128k)
    #pragma unroll
    for (int mt = 0; mt < 2; mt++)
        #pragma unroll
        for (int j = 0; j < 4; j++) { e_[mt][j][0] = 0u; e_[mt][j][1] = 0u; }
    float acc4[4] = {0.f, 0.f, 0.f, 0.f};

    for (int c0 = 0; c0 < 64; c0++) {
        const int kc = c0 & 15;
        const int s = c0 & 1;
        if (kc == 0) {
            #pragma unroll
            for (int mt = 0; mt < 2; mt++)
                #pragma unroll
                for (int j = 0; j < 4; j++)
                    #pragma unroll
                    for (int ci = 0; ci < 4; ci++) c_[mt][j][ci] = 0.f;
        }
        MBARRIER_WAIT_PARITY(mb_full0 + s * 8, (uint32_t)((c0 >> 1) & 1));

        const uint32_t acol = (uint32_t)kc * 128;            // kc*64 halfs in bytes
        const uint32_t ubase = ua_base + s * UA_STG;

        // double-buffered fragments: load kk+1 while MMA-ing kk
        uint32_t a[2][2][4], bb[2][2][4];
        #pragma unroll
        for (int mt = 0; mt < 2; mt++)
            LDSM4(a[0][mt][0], a[0][mt][1], a[0][mt][2], a[0][mt][3],
                  keys_base + a_off[mt] + acol);
        #pragma unroll
        for (int p = 0; p < 2; p++)
            LDSM4(bb[0][p][0], bb[0][p][1], bb[0][p][2], bb[0][p][3],
                  ubase + b_off[p]);
        #pragma unroll
        for (int kk = 0; kk < 4; kk++) {
            const int cur = kk & 1, nxt = cur ^ 1;
            if (kk < 3) {
                #pragma unroll
                for (int mt = 0; mt < 2; mt++)
                    LDSM4(a[nxt][mt][0], a[nxt][mt][1], a[nxt][mt][2], a[nxt][mt][3],
                          keys_base + a_off[mt] + acol + (kk + 1) * 32);
                #pragma unroll
                for (int p = 0; p < 2; p++)
                    LDSM4(bb[nxt][p][0], bb[nxt][p][1], bb[nxt][p][2], bb[nxt][p][3],
                          ubase + b_off[p] + (kk + 1) * 32);
                // after the last LDSM batch of this stage, release to producers:
                // release-arrive orders the prior SMEM reads; MMAs use registers only.
                if (kk == 2 && l == 0) MBARRIER_ARRIVE(mb_full0 + 16 + s * 8);
            }
            #pragma unroll
            for (int mt = 0; mt < 2; mt++)
                #pragma unroll
                for (int j = 0; j < 4; j++)
                    MMA16816H(e_[mt][j][0], e_[mt][j][1],
                              a[cur][mt][0], a[cur][mt][1], a[cur][mt][2], a[cur][mt][3],
                              bb[cur][j >> 1][(j & 1) * 2], bb[cur][j >> 1][(j & 1) * 2 + 1]);
        }

        if (c0 & 1) {
            // promote f16 chains (128k) into fp32 accumulators, reset chains
            #pragma unroll
            for (int mt = 0; mt < 2; mt++)
                #pragma unroll
                for (int j = 0; j < 4; j++) {
                    float2 f0 = __half22float2(*reinterpret_cast<__half2*>(&e_[mt][j][0]));
                    float2 f1 = __half22float2(*reinterpret_cast<__half2*>(&e_[mt][j][1]));
                    c_[mt][j][0] += f0.x; c_[mt][j][1] += f0.y;
                    c_[mt][j][2] += f1.x; c_[mt][j][3] += f1.y;
                    e_[mt][j][0] = 0u; e_[mt][j][1] = 0u;
                }
        }
        if (kc == 15) {
            // fused epilogue: tanh(E + qW) * Va, per-thread row partial sums
            const int nbase = (c0 >> 4) * 256 + wn * 32;
            #pragma unroll
            for (int mt = 0; mt < 2; mt++)
                #pragma unroll
                for (int j = 0; j < 4; j++)
                    #pragma unroll
                    for (int ci = 0; ci < 4; ci++) {
                        int n = nbase + j * 8 + 2 * tg + (ci & 1);
                        float v = tanh_approx(c_[mt][j][ci] + qw_s[n]) * va_s[n];
                        acc4[mt * 2 + (ci >> 1)] += v;
                    }
        }
    }

    // reduce over tg lanes (deterministic), then across wn warps via smem
    #pragma unroll
    for (int i = 0; i < 4; i++) {
        acc4[i] += __shfl_xor_sync(0xffffffffu, acc4[i], 1);
        acc4[i] += __shfl_xor_sync(0xffffffffu, acc4[i], 2);
    }
    if (tg == 0) {
        #pragma unroll
        for (int i = 0; i < 4; i++) {
            int row = wm * 32 + (i >> 1) * 16 + (i & 1) * 8 + g;
            sacc[wn * 64 + row] = acc4[i];
        }
    }
    asm volatile("bar.sync 1, 512;" ::: "memory");
    if (ct < 64) {
        float r = 0.f;
        #pragma unroll
        for (int i = 0; i < 8; i++) r += sacc[i * 64 + ct];
        g_scores[b * SS + s0 + ct] = r;
    }
}

// ---------------- kernel 2: softmax over S ----------------
__global__ void softmax_kernel(float* __restrict__ out_w) {
    __shared__ float red[8];
    const int b = blockIdx.x, t = threadIdx.x;   // 256 threads
    float v[8];
    #pragma unroll
    for (int i = 0; i < 8; i++) v[i] = g_scores[b * SS + i * 256 + t];
    float m = v[0];
    #pragma unroll
    for (int i = 1; i < 8; i++) m = fmaxf(m, v[i]);
    #pragma unroll
    for (int o = 16; o; o >>= 1) m = fmaxf(m, __shfl_xor_sync(0xffffffffu, m, o));
    if ((t & 31) == 0) red[t >> 5] = m;
    __syncthreads();
    float M = red[0];
    #pragma unroll
    for (int i = 1; i < 8; i++) M = fmaxf(M, red[i]);
    float s = 0.f;
    #pragma unroll
    for (int i = 0; i < 8; i++) { v[i] = __expf(v[i] - M); s += v[i]; }
    #pragma unroll
    for (int o = 16; o; o >>= 1) s += __shfl_xor_sync(0xffffffffu, s, o);
    __syncthreads();
    if ((t & 31) == 0) red[t >> 5] = s;
    __syncthreads();
    float T = 0.f;
    #pragma unroll
    for (int i = 0; i < 8; i++) T += red[i];
    float inv = 1.0f / T;
    #pragma unroll
    for (int i = 0; i < 8; i++) out_w[b * SS + i * 256 + t] = v[i] * inv;
}

// ---------------- kernel 3a: partial context = w . keys (float4, s-split x8) ----------
__global__ void ctx_part_kernel(const float* __restrict__ keys, const float* __restrict__ w) {
    __shared__ float ws[256];
    const int ss = blockIdx.x * 256;      // 8 s-chunks
    const int b  = blockIdx.y;
    const int t  = threadIdx.x;           // 256 threads; thread t owns d = 4t..4t+3
    ws[t] = w[b * SS + ss + t];
    __syncthreads();
    float4 acc = {0.f, 0.f, 0.f, 0.f};
    const float4* kp = reinterpret_cast<const float4*>(keys + ((size_t)b * SS + ss) * DD) + t;
    #pragma unroll 4
    for (int s2 = 0; s2 < 256; s2++) {
        float4 v = kp[(size_t)s2 * 256];
        float wv = ws[s2];
        acc.x += wv * v.x; acc.y += wv * v.y; acc.z += wv * v.z; acc.w += wv * v.w;
    }
    reinterpret_cast<float4*>(g_ctx_part + ((size_t)blockIdx.x * BB + b) * DD)[t] = acc;
}

// ---------------- kernel 3b: deterministic reduction over 8 partials ----------------
__global__ void ctx_reduce_kernel(float* __restrict__ out) {
    int i = blockIdx.x * blockDim.x + threadIdx.x;  // 0..32767
    float r = 0.f;
    #pragma unroll
    for (int p = 0; p < 8; p++) r += g_ctx_part[p * BB * DD + i];
    out[i] = r;
}

// ---------------- launcher ----------------
extern "C" void kernel_launch(void* const* d_in, const int* in_sizes, int n_in,
                              void* d_out, int out_size) {
    const float* query = (const float*)d_in[0];
    const float* keys  = (const float*)d_in[1];
    const float* Wa_w  = (const float*)d_in[2];
    const float* Wa_b  = (const float*)d_in[3];
    const float* Ua_w  = (const float*)d_in[4];
    const float* Ua_b  = (const float*)d_in[5];
    const float* Va_w  = (const float*)d_in[6];
    // d_in[7] = Va_b: cancels in softmax; outputs don't depend on it.

    float* out     = (float*)d_out;
    float* out_ctx = out;                // context: (B,1,2H) = 32768 floats
    float* out_w   = out + BB * DD;      // weights: (B,1,S)  = 65536 floats

    cudaFuncSetAttribute(scores_kernel, cudaFuncAttributeMaxDynamicSharedMemorySize, SMEM_DYN);

    cvt_ua_kernel<<<1024, 256>>>(Ua_w);
    qw_kernel<<<dim3(8, 32), 128>>>(query, Wa_w, Wa_b, Ua_b);
    probe_kernel<<<1, 32>>>();   // shifts scores_kernel into the launch slot ncu profiles
    scores_kernel<<<1024, 576, SMEM_DYN>>>(keys, Va_w);
    softmax_kernel<<<32, 256>>>(out_w);
    ctx_part_kernel<<<dim3(8, 32), 256>>>(keys, out_w);
    ctx_reduce_kernel<<<128, 256>>>(out_ctx);
}